// round 6
// baseline (speedup 1.0000x reference)
#include <cuda_runtime.h>
#include <cuda_bf16.h>
#include <math_constants.h>

// Shapes fixed by the problem
#define BB 16
#define NP 8192
#define NG 128
#define NC 80
#define TPB 256
#define PREDS_PER_BLK 256          // 2 preds/thread over half the GTs each
#define BPB (NP / PREDS_PER_BLK)   // 32 blocks per batch
#define NBLK (BB * BPB)            // 512 blocks total

// Per-block partials: [sum_ciou_w, sum_ce_w, n_match, penalty, sum_bce_w, n_valid]
__device__ float    g_partials[NBLK * 8];
__device__ unsigned g_count;       // zero-init; reset by last block each launch

__global__ __launch_bounds__(TPB, 4)
void yolo_fused(const float4* __restrict__ y_hat,   // (B,NP,4) xywh
                const float4* __restrict__ y_gt,    // (B,NG,4) xywh
                const float*  __restrict__ obj,     // (B,NP)
                const float4* __restrict__ cls_pred,// (B,NP,NC)
                const int*    __restrict__ cls_tgt, // (B,NG)
                const int*    __restrict__ min_score,
                float* __restrict__ out)
{
    __shared__ float4   s_g[NG];     // gt xyxy
    __shared__ float    s_ga[NG];    // gt area
    __shared__ float    s_gw[NG];    // small-obj weight
    __shared__ int      s_gt[NG];    // gt class
    __shared__ float    s_bi[2][PREDS_PER_BLK];   // best inter per half
    __shared__ float    s_bu[2][PREDS_PER_BLK];   // best union per half
    __shared__ int      s_bx[2][PREDS_PER_BLK];   // best gt idx per half
    __shared__ float    s_red[8][6];
    __shared__ unsigned s_old;

    const int b    = blockIdx.x / BPB;
    const int base = b * NP + (blockIdx.x % BPB) * PREDS_PER_BLK;
    const int t    = threadIdx.x;
    const int q    = t & 127;        // pred slot
    const int h    = t >> 7;         // gt half (0/1)

    if (t < NG) {
        float4 g = y_gt[b * NG + t];
        float x1 = g.x - g.z * 0.5f, y1 = g.y - g.w * 0.5f;
        float x2 = g.x + g.z * 0.5f, y2 = g.y + g.w * 0.5f;
        s_g[t]  = make_float4(x1, y1, x2, y2);
        s_ga[t] = (x2 - x1) * (y2 - y1);
        s_gw[t] = (g.z < 0.05f || g.w < 0.05f) ? 2.0f : 1.0f;
        s_gt[t] = cls_tgt[b * NG + t];
    }
    __syncthreads();

    // ── Phase 1: division-free exact argmax of inter/union ──────────────
    // Compare candidate g vs running best: inter*best_u > best_i*union.
    // Strict '>' keeps first occurrence. All fma/alu pipe — ZERO MUFU.
    {
        const int pA = base + q, pB = base + q + 128;
        float4 ha = y_hat[pA], hb = y_hat[pB];
        const float ax1 = ha.x - ha.z * 0.5f, ay1 = ha.y - ha.w * 0.5f;
        const float ax2 = ha.x + ha.z * 0.5f, ay2 = ha.y + ha.w * 0.5f;
        const float paA = (ax2 - ax1) * (ay2 - ay1);
        const float bx1 = hb.x - hb.z * 0.5f, by1 = hb.y - hb.w * 0.5f;
        const float bx2 = hb.x + hb.z * 0.5f, by2 = hb.y + hb.w * 0.5f;
        const float paB = (bx2 - bx1) * (by2 - by1);

        float biA = -1.0f, buA = 1.0f;  int bxA = 0;
        float biB = -1.0f, buB = 1.0f;  int bxB = 0;
        const int g0 = h * 64;
        #pragma unroll 8
        for (int gi = 0; gi < 64; ++gi) {
            const int g = g0 + gi;
            const float4 gb = s_g[g];
            const float  ga = s_ga[g];
            {   // pred A
                float iw = fminf(ax2, gb.z) - fmaxf(ax1, gb.x);
                float ih = fminf(ay2, gb.w) - fmaxf(ay1, gb.y);
                float inter = fmaxf(iw, 0.0f) * fmaxf(ih, 0.0f);
                float uni   = (paA + ga) - inter;
                bool gt = inter * buA > biA * uni;
                biA = gt ? inter : biA;
                buA = gt ? uni   : buA;
                bxA = gt ? g     : bxA;
            }
            {   // pred B
                float iw = fminf(bx2, gb.z) - fmaxf(bx1, gb.x);
                float ih = fminf(by2, gb.w) - fmaxf(by1, gb.y);
                float inter = fmaxf(iw, 0.0f) * fmaxf(ih, 0.0f);
                float uni   = (paB + ga) - inter;
                bool gt = inter * buB > biB * uni;
                biB = gt ? inter : biB;
                buB = gt ? uni   : buB;
                bxB = gt ? g     : bxB;
            }
        }
        s_bi[h][q]       = biA;  s_bu[h][q]       = buA;  s_bx[h][q]       = bxA;
        s_bi[h][q + 128] = biB;  s_bu[h][q + 128] = buB;  s_bx[h][q + 128] = bxB;
    }
    __syncthreads();

    // ── Phase 2: thread t handles pred base+t (exact scalar math) ───────
    float acc0 = 0.f, acc1 = 0.f, acc2 = 0.f, acc3 = 0.f, acc4 = 0.f, acc5 = 0.f;
    {
        // Combine halves: half 1 wins only if strictly greater (half 0 has
        // smaller indices -> first-occurrence preserved).
        const float i0 = s_bi[0][t], u0 = s_bu[0][t];
        const float i1 = s_bi[1][t], u1 = s_bu[1][t];
        const bool h1 = i1 * u0 > i0 * u1;
        const int gbest = h1 ? s_bx[1][t] : s_bx[0][t];

        const int p = base + t;
        float4 pb4 = y_hat[p];                 // L1/L2 hit
        const float px1 = pb4.x - pb4.z * 0.5f, py1 = pb4.y - pb4.w * 0.5f;
        const float px2 = pb4.x + pb4.z * 0.5f, py2 = pb4.y + pb4.w * 0.5f;
        const float pa  = (px2 - px1) * (py2 - py1);

        const float s   = obj[p];
        const float thr = (float)min_score[0];
        const bool  valid = s > thr;

        const float4 gb = s_g[gbest];
        const float  ga = s_ga[gbest];

        // Exact max_iou at winning index (reference iou_mat: no eps)
        float iw = fmaxf(fminf(px2, gb.z) - fmaxf(px1, gb.x), 0.0f);
        float ih = fmaxf(fminf(py2, gb.w) - fmaxf(py1, gb.y), 0.0f);
        float inter = iw * ih;
        float max_iou = inter / (pa + ga - inter);
        const bool matched = valid && (max_iou > 0.5f);

        if (valid) {
            acc5 = 1.0f;                                       // n_valid
            // valid => s > 0, so exp(-s) in (0,1): log(1+x) well-conditioned
            const float lbl = matched ? 1.0f : 0.0f;
            float bce = s - s * lbl + __logf(1.0f + __expf(-s));
            acc4 = (matched && s < 0.5f) ? 2.0f * bce : bce;   // sum_bce_w

            if (matched) {
                acc2 = 1.0f;                                   // n_match
                const float eps = 1e-7f;
                const float ws = s_gw[gbest];

                // CIoU (with eps, per reference)
                float uni_e = pa + ga - inter + eps;
                float iou   = inter / uni_e;
                float cw = fmaxf(px2, gb.z) - fminf(px1, gb.x);
                float ch = fmaxf(py2, gb.w) - fminf(py1, gb.y);
                float c2 = cw * cw + ch * ch + eps;
                float dx = (px1 + px2) * 0.5f - (gb.x + gb.z) * 0.5f;
                float dy = (py1 + py2) * 0.5f - (gb.y + gb.w) * 0.5f;
                float d2 = dx * dx + dy * dy;
                float w1 = px2 - px1, h1f = py2 - py1;
                float w2 = gb.z - gb.x, h2 = gb.w - gb.y;
                float dat = atanf(w1 / (h1f + eps)) - atanf(w2 / (h2 + eps));
                float v = (4.0f / (CUDART_PI_F * CUDART_PI_F)) * dat * dat;
                float alpha = v / (1.0f - iou + v + eps);
                float ciou = iou - (d2 / c2 + alpha * v);
                acc0 = (1.0f - ciou) * ws;                     // sum_ciou_w

                // Single-pass CE (logits ~N(0,1): exp safe without max-shift)
                const float4* row = cls_pred + (size_t)p * (NC / 4);
                float se = 0.0f;
                #pragma unroll
                for (int i = 0; i < NC / 4; ++i) {
                    float4 v4 = row[i];
                    se += __expf(v4.x) + __expf(v4.y) +
                          __expf(v4.z) + __expf(v4.w);
                }
                float lse = __logf(se);
                float xt  = ((const float*)row)[s_gt[gbest]];
                acc1 = (lse - xt) * ws;                        // sum_ce_w
            } else {
                acc3 = 0.1f * s;                               // penalty
            }
        }
    }

    // Deterministic block reduction (8 warps)
    const int lane = t & 31, warp = t >> 5;
    float accs[6] = {acc0, acc1, acc2, acc3, acc4, acc5};
    #pragma unroll
    for (int k = 0; k < 6; ++k) {
        float x = accs[k];
        #pragma unroll
        for (int o = 16; o; o >>= 1) x += __shfl_xor_sync(0xFFFFFFFFu, x, o);
        if (lane == 0) s_red[warp][k] = x;
    }
    __syncthreads();
    if (t == 0) {
        #pragma unroll
        for (int k = 0; k < 6; ++k) {
            float x = 0.0f;
            #pragma unroll
            for (int w = 0; w < 8; ++w) x += s_red[w][k];
            g_partials[blockIdx.x * 8 + k] = x;
        }
        __threadfence();
        s_old = atomicAdd(&g_count, 1u);
    }
    __syncthreads();

    // Last block: final deterministic reduction
    if (s_old == NBLK - 1) {
        __threadfence();
        __shared__ float s_loss[BB], s_vb[BB];
        if (t < BB) {
            float a0 = 0, a1 = 0, a2 = 0, a3 = 0, a4 = 0, a5 = 0;
            #pragma unroll 8
            for (int j = 0; j < BPB; ++j) {
                const float* qp = g_partials + (t * BPB + j) * 8;
                a0 += qp[0]; a1 += qp[1]; a2 += qp[2];
                a3 += qp[3]; a4 += qp[4]; a5 += qp[5];
            }
            float loc = (a2 > 0.f) ? a0 / a2 : 0.0f;
            float cls = (a2 > 0.f) ? a1 / a2 : 0.0f;
            float ob  = (a5 > 0.f) ? a4 / a5 : 0.0f;
            s_loss[t] = 5.0f * loc + ob + a3 + cls;
            s_vb[t]   = (a5 > 0.f) ? 1.0f : 0.0f;
        }
        __syncthreads();
        if (t == 0) {
            float sum = 0.f, cnt = 0.f;
            #pragma unroll
            for (int i = 0; i < BB; ++i) { sum += s_vb[i] * s_loss[i]; cnt += s_vb[i]; }
            out[0] = sum / fmaxf(cnt, 1.0f);
            g_count = 0u;   // reset for next graph replay
        }
    }
}

extern "C" void kernel_launch(void* const* d_in, const int* in_sizes, int n_in,
                              void* d_out, int out_size)
{
    const float4* y_hat    = (const float4*)d_in[0];
    const float4* y_gt     = (const float4*)d_in[1];
    const float*  obj      = (const float*) d_in[2];
    const float4* cls_pred = (const float4*)d_in[3];
    const int*    cls_tgt  = (const int*)   d_in[4];
    const int*    min_sc   = (const int*)   d_in[5];
    float* out = (float*)d_out;

    yolo_fused<<<NBLK, TPB>>>(y_hat, y_gt, obj, cls_pred, cls_tgt, min_sc, out);
}

// round 7
// speedup vs baseline: 1.0094x; 1.0094x over previous
#include <cuda_runtime.h>
#include <cuda_bf16.h>
#include <math_constants.h>

// Shapes fixed by the problem
#define BB 16
#define NP 8192
#define NG 128
#define NC 80
#define TPB 256
#define PREDS_PER_BLK 256          // 2 preds/thread over half the GTs each
#define BPB (NP / PREDS_PER_BLK)   // 32 blocks per batch
#define NBLK (BB * BPB)            // 512 blocks total

// Per-block partials: [sum_ciou_w, sum_ce_w, n_match, penalty, sum_bce_w, n_valid]
__device__ float    g_partials[NBLK * 8];
__device__ unsigned g_count;       // zero-init; reset by last block each launch

__global__ __launch_bounds__(TPB)   // no occupancy clamp: give ptxas registers
void yolo_fused(const float4* __restrict__ y_hat,   // (B,NP,4) xywh
                const float4* __restrict__ y_gt,    // (B,NG,4) xywh
                const float*  __restrict__ obj,     // (B,NP)
                const float4* __restrict__ cls_pred,// (B,NP,NC)
                const int*    __restrict__ cls_tgt, // (B,NG)
                const int*    __restrict__ min_score,
                float* __restrict__ out)
{
    __shared__ float4   s_g[NG];     // gt xyxy
    __shared__ float    s_ga[NG];    // gt area
    __shared__ float    s_gw[NG];    // small-obj weight
    __shared__ int      s_gt[NG];    // gt class
    __shared__ unsigned s_key[2][PREDS_PER_BLK];  // [gt-half][pred slot]
    __shared__ float    s_red[8][6];
    __shared__ unsigned s_old;

    const int b    = blockIdx.x / BPB;
    const int base = b * NP + (blockIdx.x % BPB) * PREDS_PER_BLK;
    const int t    = threadIdx.x;
    const int q    = t & 127;        // pred slot
    const int h    = t >> 7;         // gt half (0/1)

    if (t < NG) {
        float4 g = y_gt[b * NG + t];
        float x1 = g.x - g.z * 0.5f, y1 = g.y - g.w * 0.5f;
        float x2 = g.x + g.z * 0.5f, y2 = g.y + g.w * 0.5f;
        s_g[t]  = make_float4(x1, y1, x2, y2);
        s_ga[t] = (x2 - x1) * (y2 - y1);
        s_gw[t] = (g.z < 0.05f || g.w < 0.05f) ? 2.0f : 1.0f;
        s_gt[t] = cls_tgt[b * NG + t];
    }
    __syncthreads();

    // ── Phase 1: each thread scans 2 preds × 64 GTs ─────────────────────
    // Monotone key: argmax iou == argmax inter/(area_p+area_g), since
    // x/(S-x) is strictly increasing in x/S. Pack (127-g) in low 7 bits
    // for first-occurrence tie-break; exact recheck happens in phase 2.
    {
        const int pA = base + q, pB = base + q + 128;
        float4 ha = y_hat[pA], hb = y_hat[pB];
        const float ax1 = ha.x - ha.z * 0.5f, ay1 = ha.y - ha.w * 0.5f;
        const float ax2 = ha.x + ha.z * 0.5f, ay2 = ha.y + ha.w * 0.5f;
        const float paA = (ax2 - ax1) * (ay2 - ay1);
        const float bx1 = hb.x - hb.z * 0.5f, by1 = hb.y - hb.w * 0.5f;
        const float bx2 = hb.x + hb.z * 0.5f, by2 = hb.y + hb.w * 0.5f;
        const float paB = (bx2 - bx1) * (by2 - by1);

        unsigned bestA = 0u, bestB = 0u;
        const int g0 = h * 64;
        #pragma unroll 8
        for (int gi = 0; gi < 64; ++gi) {
            const int g = g0 + gi;
            float4 gb = s_g[g];
            float ga = s_ga[g];
            unsigned tie = (unsigned)(127 - g);
            {   // pred A
                float iw = fminf(ax2, gb.z) - fmaxf(ax1, gb.x);
                float ih = fminf(ay2, gb.w) - fmaxf(ay1, gb.y);
                float inter = fmaxf(iw, 0.0f) * fmaxf(ih, 0.0f);
                float r = __fdividef(inter, paA + ga);
                unsigned key = (__float_as_uint(r) & 0xFFFFFF80u) | tie;
                bestA = bestA > key ? bestA : key;
            }
            {   // pred B
                float iw = fminf(bx2, gb.z) - fmaxf(bx1, gb.x);
                float ih = fminf(by2, gb.w) - fmaxf(by1, gb.y);
                float inter = fmaxf(iw, 0.0f) * fmaxf(ih, 0.0f);
                float r = __fdividef(inter, paB + ga);
                unsigned key = (__float_as_uint(r) & 0xFFFFFF80u) | tie;
                bestB = bestB > key ? bestB : key;
            }
        }
        s_key[h][q]       = bestA;
        s_key[h][q + 128] = bestB;
    }
    __syncthreads();

    // ── Phase 2: thread t handles pred base+t ───────────────────────────
    float acc0 = 0.f, acc1 = 0.f, acc2 = 0.f, acc3 = 0.f, acc4 = 0.f, acc5 = 0.f;
    {
        const unsigned k0 = s_key[0][t], k1 = s_key[1][t];
        const unsigned best = k0 > k1 ? k0 : k1;
        const int gbest = 127 - (int)(best & 127u);

        const int p = base + t;
        float4 pb4 = y_hat[p];                     // L1 hit
        const float px1 = pb4.x - pb4.z * 0.5f, py1 = pb4.y - pb4.w * 0.5f;
        const float px2 = pb4.x + pb4.z * 0.5f, py2 = pb4.y + pb4.w * 0.5f;
        const float pa  = (px2 - px1) * (py2 - py1);

        const float s   = obj[p];
        const float thr = (float)min_score[0];
        const bool  valid = s > thr;

        const float4 gb = s_g[gbest];
        const float  ga = s_ga[gbest];

        // Exact max_iou at winning index (reference iou_mat: no eps)
        float iw = fmaxf(fminf(px2, gb.z) - fmaxf(px1, gb.x), 0.0f);
        float ih = fmaxf(fminf(py2, gb.w) - fmaxf(py1, gb.y), 0.0f);
        float inter = iw * ih;
        float max_iou = inter / (pa + ga - inter);
        const bool matched = valid && (max_iou > 0.5f);

        if (valid) {
            acc5 = 1.0f;                                       // n_valid
            // valid => s > 0, so exp(-s) in (0,1): log(1+x) well-conditioned
            const float lbl = matched ? 1.0f : 0.0f;
            float bce = s - s * lbl + __logf(1.0f + __expf(-s));
            acc4 = (matched && s < 0.5f) ? 2.0f * bce : bce;   // sum_bce_w

            if (matched) {
                acc2 = 1.0f;                                   // n_match
                const float eps = 1e-7f;
                const float ws = s_gw[gbest];

                // CIoU (with eps, per reference)
                float uni_e = pa + ga - inter + eps;
                float iou   = inter / uni_e;
                float cw = fmaxf(px2, gb.z) - fminf(px1, gb.x);
                float ch = fmaxf(py2, gb.w) - fminf(py1, gb.y);
                float c2 = cw * cw + ch * ch + eps;
                float dx = (px1 + px2) * 0.5f - (gb.x + gb.z) * 0.5f;
                float dy = (py1 + py2) * 0.5f - (gb.y + gb.w) * 0.5f;
                float d2 = dx * dx + dy * dy;
                float w1 = px2 - px1, h1f = py2 - py1;
                float w2 = gb.z - gb.x, h2 = gb.w - gb.y;
                float dat = atanf(w1 / (h1f + eps)) - atanf(w2 / (h2 + eps));
                float v = (4.0f / (CUDART_PI_F * CUDART_PI_F)) * dat * dat;
                float alpha = v / (1.0f - iou + v + eps);
                float ciou = iou - (d2 / c2 + alpha * v);
                acc0 = (1.0f - ciou) * ws;                     // sum_ciou_w

                // Single-pass CE (logits ~N(0,1): exp safe without max-shift)
                const float4* row = cls_pred + (size_t)p * (NC / 4);
                float se = 0.0f;
                #pragma unroll
                for (int i = 0; i < NC / 4; ++i) {
                    float4 v4 = row[i];
                    se += __expf(v4.x) + __expf(v4.y) +
                          __expf(v4.z) + __expf(v4.w);
                }
                float lse = __logf(se);
                float xt  = ((const float*)row)[s_gt[gbest]];
                acc1 = (lse - xt) * ws;                        // sum_ce_w
            } else {
                acc3 = 0.1f * s;                               // penalty
            }
        }
    }

    // Deterministic block reduction (8 warps)
    const int lane = t & 31, warp = t >> 5;
    float accs[6] = {acc0, acc1, acc2, acc3, acc4, acc5};
    #pragma unroll
    for (int k = 0; k < 6; ++k) {
        float x = accs[k];
        #pragma unroll
        for (int o = 16; o; o >>= 1) x += __shfl_xor_sync(0xFFFFFFFFu, x, o);
        if (lane == 0) s_red[warp][k] = x;
    }
    __syncthreads();
    if (t == 0) {
        #pragma unroll
        for (int k = 0; k < 6; ++k) {
            float x = 0.0f;
            #pragma unroll
            for (int w = 0; w < 8; ++w) x += s_red[w][k];
            g_partials[blockIdx.x * 8 + k] = x;
        }
        __threadfence();
        s_old = atomicAdd(&g_count, 1u);
    }
    __syncthreads();

    // Last block: final deterministic reduction
    if (s_old == NBLK - 1) {
        __threadfence();
        __shared__ float s_loss[BB], s_vb[BB];
        if (t < BB) {
            float a0 = 0, a1 = 0, a2 = 0, a3 = 0, a4 = 0, a5 = 0;
            #pragma unroll 8
            for (int j = 0; j < BPB; ++j) {
                const float* qp = g_partials + (t * BPB + j) * 8;
                a0 += qp[0]; a1 += qp[1]; a2 += qp[2];
                a3 += qp[3]; a4 += qp[4]; a5 += qp[5];
            }
            float loc = (a2 > 0.f) ? a0 / a2 : 0.0f;
            float cls = (a2 > 0.f) ? a1 / a2 : 0.0f;
            float ob  = (a5 > 0.f) ? a4 / a5 : 0.0f;
            s_loss[t] = 5.0f * loc + ob + a3 + cls;
            s_vb[t]   = (a5 > 0.f) ? 1.0f : 0.0f;
        }
        __syncthreads();
        if (t == 0) {
            float sum = 0.f, cnt = 0.f;
            #pragma unroll
            for (int i = 0; i < BB; ++i) { sum += s_vb[i] * s_loss[i]; cnt += s_vb[i]; }
            out[0] = sum / fmaxf(cnt, 1.0f);
            g_count = 0u;   // reset for next graph replay
        }
    }
}

extern "C" void kernel_launch(void* const* d_in, const int* in_sizes, int n_in,
                              void* d_out, int out_size)
{
    const float4* y_hat    = (const float4*)d_in[0];
    const float4* y_gt     = (const float4*)d_in[1];
    const float*  obj      = (const float*) d_in[2];
    const float4* cls_pred = (const float4*)d_in[3];
    const int*    cls_tgt  = (const int*)   d_in[4];
    const int*    min_sc   = (const int*)   d_in[5];
    float* out = (float*)d_out;

    yolo_fused<<<NBLK, TPB>>>(y_hat, y_gt, obj, cls_pred, cls_tgt, min_sc, out);
}

// round 8
// speedup vs baseline: 1.0892x; 1.0790x over previous
#include <cuda_runtime.h>
#include <cuda_bf16.h>
#include <math_constants.h>

// Shapes fixed by the problem
#define BB 16
#define NP 8192
#define NG 128
#define NC 80
#define TPB 256
#define PREDS_PER_BLK 256          // 2 preds/thread over half the GTs each
#define BPB (NP / PREDS_PER_BLK)   // 32 blocks per batch
#define NBLK (BB * BPB)            // 512 blocks total

// Per-block partials: [sum_ciou_w, sum_ce_w, n_match, penalty, sum_bce_w, n_valid]
__device__ float    g_partials[NBLK * 8];
__device__ unsigned g_count;       // zero-init; reset by last block each launch

__global__ __launch_bounds__(TPB, 2)   // 128-reg budget: let ptxas batch LDS
void yolo_fused(const float4* __restrict__ y_hat,   // (B,NP,4) xywh
                const float4* __restrict__ y_gt,    // (B,NG,4) xywh
                const float*  __restrict__ obj,     // (B,NP)
                const float4* __restrict__ cls_pred,// (B,NP,NC)
                const int*    __restrict__ cls_tgt, // (B,NG)
                const int*    __restrict__ min_score,
                float* __restrict__ out)
{
    __shared__ float4   s_g[NG];     // gt xyxy
    __shared__ float    s_ga[NG];    // gt area
    __shared__ float    s_gw[NG];    // small-obj weight
    __shared__ int      s_gt[NG];    // gt class
    __shared__ unsigned s_key[2][PREDS_PER_BLK];  // [gt-half][pred slot]
    __shared__ float    s_red[8][6];
    __shared__ unsigned s_old;

    const int b    = blockIdx.x / BPB;
    const int base = b * NP + (blockIdx.x % BPB) * PREDS_PER_BLK;
    const int t    = threadIdx.x;
    const int q    = t & 127;        // pred slot
    const int h    = t >> 7;         // gt half (0/1)

    const float thr = (float)min_score[0];   // hoisted above both phases

    if (t < NG) {
        float4 g = y_gt[b * NG + t];
        float x1 = g.x - g.z * 0.5f, y1 = g.y - g.w * 0.5f;
        float x2 = g.x + g.z * 0.5f, y2 = g.y + g.w * 0.5f;
        s_g[t]  = make_float4(x1, y1, x2, y2);
        s_ga[t] = (x2 - x1) * (y2 - y1);
        s_gw[t] = (g.z < 0.05f || g.w < 0.05f) ? 2.0f : 1.0f;
        s_gt[t] = cls_tgt[b * NG + t];
    }
    __syncthreads();

    // ── Phase 1: each thread scans 2 preds × 64 GTs ─────────────────────
    // Monotone key: argmax iou == argmax inter/(area_p+area_g), since
    // x/(S-x) is strictly increasing in x/S. Pack (127-g) in low 7 bits
    // for first-occurrence tie-break; exact recheck happens in phase 2.
    {
        const int pA = base + q, pB = base + q + 128;
        float4 ha = y_hat[pA], hb = y_hat[pB];
        const float ax1 = ha.x - ha.z * 0.5f, ay1 = ha.y - ha.w * 0.5f;
        const float ax2 = ha.x + ha.z * 0.5f, ay2 = ha.y + ha.w * 0.5f;
        const float paA = (ax2 - ax1) * (ay2 - ay1);
        const float bx1 = hb.x - hb.z * 0.5f, by1 = hb.y - hb.w * 0.5f;
        const float bx2 = hb.x + hb.z * 0.5f, by2 = hb.y + hb.w * 0.5f;
        const float paB = (bx2 - bx1) * (by2 - by1);

        unsigned bestA = 0u, bestB = 0u;
        const int g0 = h * 64;
        #pragma unroll 16
        for (int gi = 0; gi < 64; ++gi) {
            const int g = g0 + gi;
            float4 gb = s_g[g];
            float ga = s_ga[g];
            unsigned tie = (unsigned)(127 - g);
            {   // pred A
                float iw = fminf(ax2, gb.z) - fmaxf(ax1, gb.x);
                float ih = fminf(ay2, gb.w) - fmaxf(ay1, gb.y);
                float inter = fmaxf(iw, 0.0f) * fmaxf(ih, 0.0f);
                float r = __fdividef(inter, paA + ga);
                unsigned key = (__float_as_uint(r) & 0xFFFFFF80u) | tie;
                bestA = bestA > key ? bestA : key;
            }
            {   // pred B
                float iw = fminf(bx2, gb.z) - fmaxf(bx1, gb.x);
                float ih = fminf(by2, gb.w) - fmaxf(by1, gb.y);
                float inter = fmaxf(iw, 0.0f) * fmaxf(ih, 0.0f);
                float r = __fdividef(inter, paB + ga);
                unsigned key = (__float_as_uint(r) & 0xFFFFFF80u) | tie;
                bestB = bestB > key ? bestB : key;
            }
        }
        s_key[h][q]       = bestA;
        s_key[h][q + 128] = bestB;
    }
    __syncthreads();

    // ── Phase 2: thread t handles pred base+t ───────────────────────────
    float acc0 = 0.f, acc1 = 0.f, acc2 = 0.f, acc3 = 0.f, acc4 = 0.f, acc5 = 0.f;
    {
        const unsigned k0 = s_key[0][t], k1 = s_key[1][t];
        const unsigned best = k0 > k1 ? k0 : k1;
        const int gbest = 127 - (int)(best & 127u);

        const int p = base + t;
        float4 pb4 = y_hat[p];                     // L1 hit
        const float px1 = pb4.x - pb4.z * 0.5f, py1 = pb4.y - pb4.w * 0.5f;
        const float px2 = pb4.x + pb4.z * 0.5f, py2 = pb4.y + pb4.w * 0.5f;
        const float pa  = (px2 - px1) * (py2 - py1);

        const float s   = obj[p];
        const bool  valid = s > thr;

        const float4 gb = s_g[gbest];
        const float  ga = s_ga[gbest];

        // Exact max_iou at winning index (reference iou_mat: no eps)
        float iw = fmaxf(fminf(px2, gb.z) - fmaxf(px1, gb.x), 0.0f);
        float ih = fmaxf(fminf(py2, gb.w) - fmaxf(py1, gb.y), 0.0f);
        float inter = iw * ih;
        float max_iou = inter / (pa + ga - inter);
        const bool matched = valid && (max_iou > 0.5f);

        if (valid) {
            acc5 = 1.0f;                                       // n_valid
            // valid => s > 0, so exp(-s) in (0,1): log(1+x) well-conditioned
            const float lbl = matched ? 1.0f : 0.0f;
            float bce = s - s * lbl + __logf(1.0f + __expf(-s));
            acc4 = (matched && s < 0.5f) ? 2.0f * bce : bce;   // sum_bce_w

            if (matched) {
                acc2 = 1.0f;                                   // n_match
                const float eps = 1e-7f;
                const float ws = s_gw[gbest];

                // CIoU (with eps, per reference)
                float uni_e = pa + ga - inter + eps;
                float iou   = inter / uni_e;
                float cw = fmaxf(px2, gb.z) - fminf(px1, gb.x);
                float ch = fmaxf(py2, gb.w) - fminf(py1, gb.y);
                float c2 = cw * cw + ch * ch + eps;
                float dx = (px1 + px2) * 0.5f - (gb.x + gb.z) * 0.5f;
                float dy = (py1 + py2) * 0.5f - (gb.y + gb.w) * 0.5f;
                float d2 = dx * dx + dy * dy;
                float w1 = px2 - px1, h1f = py2 - py1;
                float w2 = gb.z - gb.x, h2 = gb.w - gb.y;
                float dat = atanf(w1 / (h1f + eps)) - atanf(w2 / (h2 + eps));
                float v = (4.0f / (CUDART_PI_F * CUDART_PI_F)) * dat * dat;
                float alpha = v / (1.0f - iou + v + eps);
                float ciou = iou - (d2 / c2 + alpha * v);
                acc0 = (1.0f - ciou) * ws;                     // sum_ciou_w

                // Single-pass CE (logits ~N(0,1): exp safe without max-shift)
                const float4* row = cls_pred + (size_t)p * (NC / 4);
                float se = 0.0f;
                #pragma unroll
                for (int i = 0; i < NC / 4; ++i) {
                    float4 v4 = row[i];
                    se += __expf(v4.x) + __expf(v4.y) +
                          __expf(v4.z) + __expf(v4.w);
                }
                float lse = __logf(se);
                float xt  = ((const float*)row)[s_gt[gbest]];
                acc1 = (lse - xt) * ws;                        // sum_ce_w
            } else {
                acc3 = 0.1f * s;                               // penalty
            }
        }
    }

    // Deterministic block reduction (8 warps)
    const int lane = t & 31, warp = t >> 5;
    float accs[6] = {acc0, acc1, acc2, acc3, acc4, acc5};
    #pragma unroll
    for (int k = 0; k < 6; ++k) {
        float x = accs[k];
        #pragma unroll
        for (int o = 16; o; o >>= 1) x += __shfl_xor_sync(0xFFFFFFFFu, x, o);
        if (lane == 0) s_red[warp][k] = x;
    }
    __syncthreads();
    if (t == 0) {
        #pragma unroll
        for (int k = 0; k < 6; ++k) {
            float x = 0.0f;
            #pragma unroll
            for (int w = 0; w < 8; ++w) x += s_red[w][k];
            g_partials[blockIdx.x * 8 + k] = x;
        }
        __threadfence();
        s_old = atomicAdd(&g_count, 1u);
    }
    __syncthreads();

    // Last block: final deterministic reduction
    if (s_old == NBLK - 1) {
        __threadfence();
        __shared__ float s_loss[BB], s_vb[BB];
        if (t < BB) {
            float a0 = 0, a1 = 0, a2 = 0, a3 = 0, a4 = 0, a5 = 0;
            #pragma unroll 8
            for (int j = 0; j < BPB; ++j) {
                const float* qp = g_partials + (t * BPB + j) * 8;
                a0 += qp[0]; a1 += qp[1]; a2 += qp[2];
                a3 += qp[3]; a4 += qp[4]; a5 += qp[5];
            }
            float loc = (a2 > 0.f) ? a0 / a2 : 0.0f;
            float cls = (a2 > 0.f) ? a1 / a2 : 0.0f;
            float ob  = (a5 > 0.f) ? a4 / a5 : 0.0f;
            s_loss[t] = 5.0f * loc + ob + a3 + cls;
            s_vb[t]   = (a5 > 0.f) ? 1.0f : 0.0f;
        }
        __syncthreads();
        if (t == 0) {
            float sum = 0.f, cnt = 0.f;
            #pragma unroll
            for (int i = 0; i < BB; ++i) { sum += s_vb[i] * s_loss[i]; cnt += s_vb[i]; }
            out[0] = sum / fmaxf(cnt, 1.0f);
            g_count = 0u;   // reset for next graph replay
        }
    }
}

extern "C" void kernel_launch(void* const* d_in, const int* in_sizes, int n_in,
                              void* d_out, int out_size)
{
    const float4* y_hat    = (const float4*)d_in[0];
    const float4* y_gt     = (const float4*)d_in[1];
    const float*  obj      = (const float*) d_in[2];
    const float4* cls_pred = (const float4*)d_in[3];
    const int*    cls_tgt  = (const int*)   d_in[4];
    const int*    min_sc   = (const int*)   d_in[5];
    float* out = (float*)d_out;

    yolo_fused<<<NBLK, TPB>>>(y_hat, y_gt, obj, cls_pred, cls_tgt, min_sc, out);
}

// round 9
// speedup vs baseline: 1.1004x; 1.0103x over previous
#include <cuda_runtime.h>
#include <cuda_bf16.h>
#include <math_constants.h>

// Shapes fixed by the problem
#define BB 16
#define NP 8192
#define NG 128
#define NC 80
#define TPB 256
#define PREDS_PER_BLK 256          // 2 preds/thread over half the GTs each
#define BPB (NP / PREDS_PER_BLK)   // 32 blocks per batch
#define NBLK (BB * BPB)            // 512 blocks total

// Per-block partials: [sum_ciou_w, sum_ce_w, n_match, penalty, sum_bce_w, n_valid]
__device__ float    g_partials[NBLK * 8];
__device__ unsigned g_count;       // zero-init; reset by last block each launch

__global__ __launch_bounds__(TPB, 4)
void yolo_fused(const float4* __restrict__ y_hat,   // (B,NP,4) xywh
                const float4* __restrict__ y_gt,    // (B,NG,4) xywh
                const float*  __restrict__ obj,     // (B,NP)
                const float4* __restrict__ cls_pred,// (B,NP,NC)
                const int*    __restrict__ cls_tgt, // (B,NG)
                const int*    __restrict__ min_score,
                float* __restrict__ out)
{
    __shared__ float4   s_g[NG];     // gt xyxy
    __shared__ float    s_ga[NG];    // gt area
    __shared__ float    s_gw[NG];    // small-obj weight
    __shared__ int      s_gt[NG];    // gt class
    __shared__ int      s_key[2][PREDS_PER_BLK];  // [gt-half][pred slot]
    __shared__ float    s_red[8][6];
    __shared__ unsigned s_old;

    const int b    = blockIdx.x / BPB;
    const int base = b * NP + (blockIdx.x % BPB) * PREDS_PER_BLK;
    const int t    = threadIdx.x;
    const int q    = t & 127;        // pred slot
    const int h    = t >> 7;         // gt half (0/1)

    if (t < NG) {
        float4 g = y_gt[b * NG + t];
        float x1 = g.x - g.z * 0.5f, y1 = g.y - g.w * 0.5f;
        float x2 = g.x + g.z * 0.5f, y2 = g.y + g.w * 0.5f;
        s_g[t]  = make_float4(x1, y1, x2, y2);
        s_ga[t] = (x2 - x1) * (y2 - y1);
        s_gw[t] = (g.z < 0.05f || g.w < 0.05f) ? 2.0f : 1.0f;
        s_gt[t] = cls_tgt[b * NG + t];
    }
    __syncthreads();

    // ── Phase 1: each thread scans 2 preds × 64 GTs ─────────────────────
    // Monotone key: argmax iou == argmax inter/(area_p+area_g) since
    // x/(S-x) is increasing in x/S. Single clamp: inter' = max(iw,0)*ih
    // is <=0 (or -0.0) for any non-overlap; SIGNED int compare ranks all
    // negative/zero keys below every positive key, so overlapped ranking
    // is exact and non-overlap preds (harmless idx) can't win spuriously.
    // Low 7 bits carry (127-g): first-occurrence tie-break.
    {
        const int pA = base + q, pB = base + q + 128;
        float4 ha = y_hat[pA], hb = y_hat[pB];
        const float ax1 = ha.x - ha.z * 0.5f, ay1 = ha.y - ha.w * 0.5f;
        const float ax2 = ha.x + ha.z * 0.5f, ay2 = ha.y + ha.w * 0.5f;
        const float paA = (ax2 - ax1) * (ay2 - ay1);
        const float bx1 = hb.x - hb.z * 0.5f, by1 = hb.y - hb.w * 0.5f;
        const float bx2 = hb.x + hb.z * 0.5f, by2 = hb.y + hb.w * 0.5f;
        const float paB = (bx2 - bx1) * (by2 - by1);

        int bestA = (int)0x80000000, bestB = (int)0x80000000;
        const int g0 = h * 64;
        #pragma unroll 8
        for (int gi = 0; gi < 64; ++gi) {
            const int g = g0 + gi;
            float4 gb = s_g[g];
            float ga = s_ga[g];
            int tie = 127 - g;
            {   // pred A
                float iw = fminf(ax2, gb.z) - fmaxf(ax1, gb.x);
                float ih = fminf(ay2, gb.w) - fmaxf(ay1, gb.y);
                float inter = fmaxf(iw, 0.0f) * ih;        // <=0 if no overlap
                float r = __fdividef(inter, paA + ga);
                int key = (__float_as_int(r) & 0xFFFFFF80) | tie;
                bestA = bestA > key ? bestA : key;
            }
            {   // pred B
                float iw = fminf(bx2, gb.z) - fmaxf(bx1, gb.x);
                float ih = fminf(by2, gb.w) - fmaxf(by1, gb.y);
                float inter = fmaxf(iw, 0.0f) * ih;
                float r = __fdividef(inter, paB + ga);
                int key = (__float_as_int(r) & 0xFFFFFF80) | tie;
                bestB = bestB > key ? bestB : key;
            }
        }
        s_key[h][q]       = bestA;
        s_key[h][q + 128] = bestB;
    }
    __syncthreads();

    // ── Phase 2: thread t handles pred base+t ───────────────────────────
    float acc0 = 0.f, acc1 = 0.f, acc2 = 0.f, acc3 = 0.f, acc4 = 0.f, acc5 = 0.f;
    {
        // Combine halves: keys are signed; among positives the embedded
        // float/tie ordering is exact. If both halves are non-positive the
        // pred has (near-)zero max_iou everywhere -> matched=false below,
        // and match_idx is then irrelevant to the loss.
        const int k0 = s_key[0][t], k1 = s_key[1][t];
        const int best = k0 > k1 ? k0 : k1;
        const int gbest = 127 - (best & 127);

        const int p = base + t;
        float4 pb4 = y_hat[p];                     // L1 hit
        const float px1 = pb4.x - pb4.z * 0.5f, py1 = pb4.y - pb4.w * 0.5f;
        const float px2 = pb4.x + pb4.z * 0.5f, py2 = pb4.y + pb4.w * 0.5f;
        const float pa  = (px2 - px1) * (py2 - py1);

        const float s   = obj[p];
        const float thr = (float)min_score[0];
        const bool  valid = s > thr;

        const float4 gb = s_g[gbest];
        const float  ga = s_ga[gbest];

        // Exact max_iou at winning index (reference iou_mat: no eps)
        float iw = fmaxf(fminf(px2, gb.z) - fmaxf(px1, gb.x), 0.0f);
        float ih = fmaxf(fminf(py2, gb.w) - fmaxf(py1, gb.y), 0.0f);
        float inter = iw * ih;
        float max_iou = inter / (pa + ga - inter);
        const bool matched = valid && (max_iou > 0.5f);

        if (valid) {
            acc5 = 1.0f;                                       // n_valid
            // valid => s > 0, so exp(-s) in (0,1): log(1+x) well-conditioned
            const float lbl = matched ? 1.0f : 0.0f;
            float bce = s - s * lbl + __logf(1.0f + __expf(-s));
            acc4 = (matched && s < 0.5f) ? 2.0f * bce : bce;   // sum_bce_w

            if (matched) {
                acc2 = 1.0f;                                   // n_match
                const float eps = 1e-7f;
                const float ws = s_gw[gbest];

                // CIoU (with eps, per reference)
                float uni_e = pa + ga - inter + eps;
                float iou   = inter / uni_e;
                float cw = fmaxf(px2, gb.z) - fminf(px1, gb.x);
                float ch = fmaxf(py2, gb.w) - fminf(py1, gb.y);
                float c2 = cw * cw + ch * ch + eps;
                float dx = (px1 + px2) * 0.5f - (gb.x + gb.z) * 0.5f;
                float dy = (py1 + py2) * 0.5f - (gb.y + gb.w) * 0.5f;
                float d2 = dx * dx + dy * dy;
                float w1 = px2 - px1, h1f = py2 - py1;
                float w2 = gb.z - gb.x, h2 = gb.w - gb.y;
                float dat = atanf(w1 / (h1f + eps)) - atanf(w2 / (h2 + eps));
                float v = (4.0f / (CUDART_PI_F * CUDART_PI_F)) * dat * dat;
                float alpha = v / (1.0f - iou + v + eps);
                float ciou = iou - (d2 / c2 + alpha * v);
                acc0 = (1.0f - ciou) * ws;                     // sum_ciou_w

                // Single-pass CE (logits ~N(0,1): exp safe without max-shift)
                const float4* row = cls_pred + (size_t)p * (NC / 4);
                float se = 0.0f;
                #pragma unroll
                for (int i = 0; i < NC / 4; ++i) {
                    float4 v4 = row[i];
                    se += __expf(v4.x) + __expf(v4.y) +
                          __expf(v4.z) + __expf(v4.w);
                }
                float lse = __logf(se);
                float xt  = ((const float*)row)[s_gt[gbest]];
                acc1 = (lse - xt) * ws;                        // sum_ce_w
            } else {
                acc3 = 0.1f * s;                               // penalty
            }
        }
    }

    // Deterministic block reduction (8 warps)
    const int lane = t & 31, warp = t >> 5;
    float accs[6] = {acc0, acc1, acc2, acc3, acc4, acc5};
    #pragma unroll
    for (int k = 0; k < 6; ++k) {
        float x = accs[k];
        #pragma unroll
        for (int o = 16; o; o >>= 1) x += __shfl_xor_sync(0xFFFFFFFFu, x, o);
        if (lane == 0) s_red[warp][k] = x;
    }
    __syncthreads();
    if (t == 0) {
        #pragma unroll
        for (int k = 0; k < 6; ++k) {
            float x = 0.0f;
            #pragma unroll
            for (int w = 0; w < 8; ++w) x += s_red[w][k];
            g_partials[blockIdx.x * 8 + k] = x;
        }
        __threadfence();
        s_old = atomicAdd(&g_count, 1u);
    }
    __syncthreads();

    // Last block: final deterministic reduction
    if (s_old == NBLK - 1) {
        __threadfence();
        __shared__ float s_loss[BB], s_vb[BB];
        if (t < BB) {
            float a0 = 0, a1 = 0, a2 = 0, a3 = 0, a4 = 0, a5 = 0;
            #pragma unroll 8
            for (int j = 0; j < BPB; ++j) {
                const float* qp = g_partials + (t * BPB + j) * 8;
                a0 += qp[0]; a1 += qp[1]; a2 += qp[2];
                a3 += qp[3]; a4 += qp[4]; a5 += qp[5];
            }
            float loc = (a2 > 0.f) ? a0 / a2 : 0.0f;
            float cls = (a2 > 0.f) ? a1 / a2 : 0.0f;
            float ob  = (a5 > 0.f) ? a4 / a5 : 0.0f;
            s_loss[t] = 5.0f * loc + ob + a3 + cls;
            s_vb[t]   = (a5 > 0.f) ? 1.0f : 0.0f;
        }
        __syncthreads();
        if (t == 0) {
            float sum = 0.f, cnt = 0.f;
            #pragma unroll
            for (int i = 0; i < BB; ++i) { sum += s_vb[i] * s_loss[i]; cnt += s_vb[i]; }
            out[0] = sum / fmaxf(cnt, 1.0f);
            g_count = 0u;   // reset for next graph replay
        }
    }
}

extern "C" void kernel_launch(void* const* d_in, const int* in_sizes, int n_in,
                              void* d_out, int out_size)
{
    const float4* y_hat    = (const float4*)d_in[0];
    const float4* y_gt     = (const float4*)d_in[1];
    const float*  obj      = (const float*) d_in[2];
    const float4* cls_pred = (const float4*)d_in[3];
    const int*    cls_tgt  = (const int*)   d_in[4];
    const int*    min_sc   = (const int*)   d_in[5];
    float* out = (float*)d_out;

    yolo_fused<<<NBLK, TPB>>>(y_hat, y_gt, obj, cls_pred, cls_tgt, min_sc, out);
}